// round 9
// baseline (speedup 1.0000x reference)
#include <cuda_runtime.h>
#include <cuda_bf16.h>
#include <cstdint>

#define SLEN 1024
#define BSZ  64
#define DM   1024
#define NH   16
#define DK   64
#define MTOT (SLEN*BSZ)   // 65536

// GEMM tiling (warp-level HMMA)
#define BM 128
#define BN 128
#define BK 32
#define NSTAGES (DM/BK)        // 32
#define GEMM_THREADS 256
#define NBUF 3

#define STAGE_BYTES 32768      // Ah 8K + Al 8K + Wh 8K + Wl 8K (bf16 tiles)
#define AH_OFF 0
#define AL_OFF 8192
#define WH_OFF 16384
#define WL_OFF 24576
#define SMEM_TOTAL (NBUF*STAGE_BYTES)   // 96KB

// ---------------- device scratch (no allocations allowed) ----------------
__device__ float g_q[(size_t)MTOT*DM];
__device__ float g_k[(size_t)MTOT*DM];
__device__ float g_v[(size_t)MTOT*DM];

__device__ __nv_bfloat16 g_gth[(size_t)MTOT*DM];
__device__ __nv_bfloat16 g_gtl[(size_t)MTOT*DM];
__device__ __nv_bfloat16 g_kh [(size_t)MTOT*DM];
__device__ __nv_bfloat16 g_kl [(size_t)MTOT*DM];
__device__ __nv_bfloat16 g_vh [(size_t)MTOT*DM];
__device__ __nv_bfloat16 g_vl [(size_t)MTOT*DM];
__device__ __nv_bfloat16 g_ch [(size_t)MTOT*DM];
__device__ __nv_bfloat16 g_cl [(size_t)MTOT*DM];

__device__ __nv_bfloat16 g_wqh[DM*DM], g_wql[DM*DM];
__device__ __nv_bfloat16 g_wkh[DM*DM], g_wkl[DM*DM];
__device__ __nv_bfloat16 g_wvh[DM*DM], g_wvl[DM*DM];
__device__ __nv_bfloat16 g_woh[DM*DM], g_wol[DM*DM];

typedef unsigned long long ull;

// ---------- packed fp32x2 helpers ----------
__device__ __forceinline__ ull pk2(float lo, float hi) {
    ull r;
    asm("mov.b64 %0, {%1, %2};" : "=l"(r) : "f"(lo), "f"(hi));
    return r;
}
__device__ __forceinline__ void upk2(float& lo, float& hi, ull v) {
    asm("mov.b64 {%0, %1}, %2;" : "=f"(lo), "=f"(hi) : "l"(v));
}
__device__ __forceinline__ ull ffma2(ull a, ull b, ull c) {
    ull d;
    asm("fma.rn.f32x2 %0, %1, %2, %3;" : "=l"(d) : "l"(a), "l"(b), "l"(c));
    return d;
}

__device__ __forceinline__ uint32_t smem_to_u32(const void* p) {
    uint32_t a;
    asm("{ .reg .u64 t; cvta.to.shared.u64 t, %1; cvt.u32.u64 %0, t; }" : "=r"(a) : "l"(p));
    return a;
}
__device__ __forceinline__ void cpasync8(uint32_t dst, const void* src) {
    asm volatile("cp.async.ca.shared.global [%0], [%1], 8;" :: "r"(dst), "l"(src) : "memory");
}
#define CP_COMMIT() asm volatile("cp.async.commit_group;" ::: "memory")
#define CP_WAIT1()  asm volatile("cp.async.wait_group 1;" ::: "memory")

// swizzled byte offset inside one GEMM tile: 64B rows, 8B chunks XORed by row&7
__device__ __forceinline__ uint32_t swz(uint32_t row, uint32_t col_elem) {
    uint32_t chunk = (col_elem >> 2) ^ (row & 7);
    return row * 64 + chunk * 8 + (col_elem & 3) * 2;
}

// truncation split: x -> hi(bf16 truncated) + lo(bf16 rn of residual)
__device__ __forceinline__ void split2(float x, float y, uint32_t& hi2, uint32_t& lo2) {
    uint32_t xb = __float_as_uint(x), yb = __float_as_uint(y);
    hi2 = __byte_perm(xb, yb, 0x7632);
    float xr = x - __uint_as_float(xb & 0xFFFF0000u);
    float yr = y - __uint_as_float(yb & 0xFFFF0000u);
    __nv_bfloat162 l = __floats2bfloat162_rn(xr, yr);
    lo2 = *reinterpret_cast<uint32_t*>(&l);
}

__device__ __forceinline__ void mma_bf16(float* d, const uint32_t* a, const uint32_t* b) {
    asm volatile(
        "mma.sync.aligned.m16n8k16.row.col.f32.bf16.bf16.f32 "
        "{%0,%1,%2,%3}, {%4,%5,%6,%7}, {%8,%9}, {%0,%1,%2,%3};"
        : "+f"(d[0]), "+f"(d[1]), "+f"(d[2]), "+f"(d[3])
        : "r"(a[0]), "r"(a[1]), "r"(a[2]), "r"(a[3]), "r"(b[0]), "r"(b[1]));
}

// ---------------- split pass: fp32 -> bf16 hi/lo arrays ----------------
__global__ __launch_bounds__(256)
void split_kernel(const float* __restrict__ X, __nv_bfloat16* __restrict__ Xh,
                  __nv_bfloat16* __restrict__ Xl, int n4) {
    int i = blockIdx.x * blockDim.x + threadIdx.x;
    if (i >= n4) return;
    float4 v = ((const float4*)X)[i];
    uint32_t h0, l0, h1, l1;
    split2(v.x, v.y, h0, l0);
    split2(v.z, v.w, h1, l1);
    ((uint2*)Xh)[i] = make_uint2(h0, h1);
    ((uint2*)Xl)[i] = make_uint2(l0, l1);
}

// ---------------- producer: cp.async one stage (4 bf16 tiles) ----------------
__device__ __forceinline__ void issue_stage(
    uint32_t sb32, int buf,
    const __nv_bfloat16* __restrict__ Ah, const __nv_bfloat16* __restrict__ Al,
    const __nv_bfloat16* __restrict__ Wh, const __nv_bfloat16* __restrict__ Wl,
    int m0, int n0, int k0, int tid)
{
    const int r  = tid >> 1;
    const int h2 = tid & 1;
    const uint32_t dbase = sb32 + (uint32_t)buf * STAGE_BYTES + (uint32_t)r * 64;
    const size_t arow = (size_t)(m0 + r) * DM + k0;
    const size_t wrow = (size_t)(n0 + r) * DM + k0;
#pragma unroll
    for (int j = 0; j < 4; j++) {
        const int c8 = h2 * 4 + j;
        const uint32_t doff = (uint32_t)((c8 ^ (r & 7)) * 8);
        const int ce = c8 * 4;
        cpasync8(dbase + AH_OFF + doff, Ah + arow + ce);
        cpasync8(dbase + AL_OFF + doff, Al + arow + ce);
        cpasync8(dbase + WH_OFF + doff, Wh + wrow + ce);
        cpasync8(dbase + WL_OFF + doff, Wl + wrow + ce);
    }
}

// ---------- split-bf16 3-pass HMMA GEMM: C = (Ah+Al)(Wh+Wl)^T + bias ----------
__global__ __launch_bounds__(GEMM_THREADS)
void gemm_tc(const __nv_bfloat16* __restrict__ Ah, const __nv_bfloat16* __restrict__ Al,
             const __nv_bfloat16* __restrict__ Wh, const __nv_bfloat16* __restrict__ Wl,
             const float* __restrict__ bias, float* __restrict__ C) {
    extern __shared__ char smem[];
    const uint32_t sb32 = smem_to_u32(smem);
    const int tid = threadIdx.x;
    const int lane = tid & 31;
    const int wid = tid >> 5;
    const int wm = wid & 1;
    const int wn = wid >> 1;
    const int g = lane >> 2;
    const int c = lane & 3;
    const int m0 = blockIdx.y * BM;
    const int n0 = blockIdx.x * BN;

    float acc[4][4][4];
#pragma unroll
    for (int mf = 0; mf < 4; mf++)
#pragma unroll
        for (int nf = 0; nf < 4; nf++)
#pragma unroll
            for (int q = 0; q < 4; q++) acc[mf][nf][q] = 0.0f;

    // prologue: prefetch stages 0 and 1
    issue_stage(sb32, 0, Ah, Al, Wh, Wl, m0, n0, 0, tid);
    CP_COMMIT();
    issue_stage(sb32, 1, Ah, Al, Wh, Wl, m0, n0, BK, tid);
    CP_COMMIT();

#pragma unroll 1
    for (int s = 0; s < NSTAGES; s++) {
        CP_WAIT1();
        __syncthreads();

        {
            char* sb = smem + (s % NBUF) * STAGE_BYTES;
            char* pAh = sb + AH_OFF; char* pAl = sb + AL_OFF;
            char* pWh = sb + WH_OFF; char* pWl = sb + WL_OFF;
#pragma unroll
            for (int kk = 0; kk < 2; kk++) {
                uint32_t ah[4][4], al[4][4], bh[4][2], bl[4][2];
                const int colk = kk * 16 + c * 2;
#pragma unroll
                for (int mf = 0; mf < 4; mf++) {
                    const uint32_t r0 = wm * 64 + mf * 16 + g;
                    ah[mf][0] = *(const uint32_t*)(pAh + swz(r0,     colk));
                    ah[mf][1] = *(const uint32_t*)(pAh + swz(r0 + 8, colk));
                    ah[mf][2] = *(const uint32_t*)(pAh + swz(r0,     colk + 8));
                    ah[mf][3] = *(const uint32_t*)(pAh + swz(r0 + 8, colk + 8));
                    al[mf][0] = *(const uint32_t*)(pAl + swz(r0,     colk));
                    al[mf][1] = *(const uint32_t*)(pAl + swz(r0 + 8, colk));
                    al[mf][2] = *(const uint32_t*)(pAl + swz(r0,     colk + 8));
                    al[mf][3] = *(const uint32_t*)(pAl + swz(r0 + 8, colk + 8));
                }
#pragma unroll
                for (int nf = 0; nf < 4; nf++) {
                    const uint32_t rn = wn * 32 + nf * 8 + g;
                    bh[nf][0] = *(const uint32_t*)(pWh + swz(rn, colk));
                    bh[nf][1] = *(const uint32_t*)(pWh + swz(rn, colk + 8));
                    bl[nf][0] = *(const uint32_t*)(pWl + swz(rn, colk));
                    bl[nf][1] = *(const uint32_t*)(pWl + swz(rn, colk + 8));
                }
#pragma unroll
                for (int mf = 0; mf < 4; mf++)
#pragma unroll
                    for (int nf = 0; nf < 4; nf++) {
                        mma_bf16(acc[mf][nf], ah[mf], bh[nf]);
                        mma_bf16(acc[mf][nf], ah[mf], bl[nf]);
                        mma_bf16(acc[mf][nf], al[mf], bh[nf]);
                    }
            }
        }

        // prefetch stage s+2 into buffer (s+2)%3 (consumed at stage s-1,
        // all warps past that point since they passed this iter's barrier)
        if (s + 2 < NSTAGES)
            issue_stage(sb32, (s + 2) % NBUF, Ah, Al, Wh, Wl, m0, n0, (s + 2) * BK, tid);
        CP_COMMIT();   // always commit to keep group numbering
    }

    float2 bvv[4];
#pragma unroll
    for (int nf = 0; nf < 4; nf++) {
        int col = n0 + wn * 32 + nf * 8 + c * 2;
        bvv[nf] = make_float2(bias[col], bias[col + 1]);
    }
#pragma unroll
    for (int mf = 0; mf < 4; mf++) {
        const int row = m0 + wm * 64 + mf * 16 + g;
#pragma unroll
        for (int nf = 0; nf < 4; nf++) {
            const int col = n0 + wn * 32 + nf * 8 + c * 2;
            float2 v0 = make_float2(acc[mf][nf][0] + bvv[nf].x, acc[mf][nf][1] + bvv[nf].y);
            float2 v1 = make_float2(acc[mf][nf][2] + bvv[nf].x, acc[mf][nf][3] + bvv[nf].y);
            *(float2*)(C + (size_t)row * DM + col) = v0;
            *(float2*)(C + (size_t)(row + 8) * DM + col) = v1;
        }
    }
}

// ---------- attention v3: 2 b-rows x 16 j per thread, split-bf16 writeout ----------
// Block = (s,h), 128 threads. tid: bp = tid>>2 (b = bp, bp+32), q = tid&3
// (j in [q*16, q*16+16)). Dot reduction over the 4 q-lanes (shfl_xor 1,2).
// smem (floats): Ks[64][64] @0, Vs[64][64] @4096, Qs[64][68] @8192.
#define KS_OFF 0
#define VS_OFF 4096
#define QS_OFF 8192
#define QS_STRIDE 68
#define ATTN_SMEM_FLOATS (QS_OFF + 64*QS_STRIDE)   // 12544 floats = 50176 B

__global__ __launch_bounds__(128)
void attn_kernel(const int* __restrict__ mask,
                 const float* __restrict__ Q, const float* __restrict__ K,
                 const float* __restrict__ V,
                 __nv_bfloat16* __restrict__ Ch, __nv_bfloat16* __restrict__ Cl) {
    extern __shared__ float sm[];
    float* Ks = sm + KS_OFF;   // [c][j], stride 64
    float* Vs = sm + VS_OFF;   // [c][j], stride 64
    float* Qs = sm + QS_OFF;   // [b][j], stride 68 (272B rows, 16B aligned)
    __shared__ float wred[2];

    const int s = blockIdx.x;
    const int h = blockIdx.y;
    const int tid = threadIdx.x;
    const int lane = tid & 31;
    const int w = tid >> 5;

    const size_t head_base = ((size_t)s * 64) * DM + (size_t)h * 64;

    // coalesced loads: warp w handles rows [w*16, w*16+16)
#pragma unroll 4
    for (int i = 0; i < 16; i++) {
        const int row = w * 16 + i;
        const float* gsrc = K + head_base + (size_t)row * DM + lane * 2;
        *(float2*)&Ks[row * 64 + lane * 2] = *(const float2*)gsrc;
        gsrc = V + head_base + (size_t)row * DM + lane * 2;
        *(float2*)&Vs[row * 64 + lane * 2] = *(const float2*)gsrc;
        gsrc = Q + head_base + (size_t)row * DM + lane * 2;
        *(float2*)&Qs[row * QS_STRIDE + lane * 2] = *(const float2*)gsrc;
    }

    if (tid < 64) {
        int mv = mask[tid * SLEN + s];
        float m = (float)(mv * mv);
#pragma unroll
        for (int off = 16; off; off >>= 1) m += __shfl_xor_sync(0xffffffffu, m, off);
        if (lane == 0) wred[w] = m;
    }
    __syncthreads();
    const bool masked = (wred[0] + wred[1]) == 0.0f;

    const int bp = tid >> 2;      // 0..31
    const int q  = tid & 3;       // j quarter
    const int jq = q * 16;

    // per-thread Q slices for b0=bp and b1=bp+32
    ull qr2[2][8];
#pragma unroll
    for (int b = 0; b < 2; b++) {
        const float* qp = &Qs[(bp + b * 32) * QS_STRIDE + jq];
#pragma unroll
        for (int i = 0; i < 4; i++) {
            ulonglong2 t = *(const ulonglong2*)(qp + i * 4);
            qr2[b][2 * i] = t.x; qr2[b][2 * i + 1] = t.y;
        }
    }

    ull at2[2][8];
#pragma unroll
    for (int b = 0; b < 2; b++)
#pragma unroll
        for (int i = 0; i < 8; i++) at2[b][i] = 0ULL;

#pragma unroll 2
    for (int cc = 0; cc < 64; cc++) {
        const float* kr = &Ks[cc * 64 + jq];
        ull kk[8];
#pragma unroll
        for (int i = 0; i < 4; i++) {
            ulonglong2 t = *(const ulonglong2*)(kr + i * 4);
            kk[2 * i] = t.x; kk[2 * i + 1] = t.y;
        }
        ull s0 = 0ULL, s1 = 0ULL;
#pragma unroll
        for (int i = 0; i < 8; i++) {
            s0 = ffma2(qr2[0][i], kk[i], s0);
            s1 = ffma2(qr2[1][i], kk[i], s1);
        }
        float lo, hi;
        upk2(lo, hi, s0); float d0 = lo + hi;
        upk2(lo, hi, s1); float d1 = lo + hi;
        d0 += __shfl_xor_sync(0xffffffffu, d0, 1);
        d0 += __shfl_xor_sync(0xffffffffu, d0, 2);
        d1 += __shfl_xor_sync(0xffffffffu, d1, 1);
        d1 += __shfl_xor_sync(0xffffffffu, d1, 2);
        const float sc0 = masked ? -1e9f : d0 * 0.125f;
        const float sc1 = masked ? -1e9f : d1 * 0.125f;
        const ull sb0 = pk2(sc0, sc0);
        const ull sb1 = pk2(sc1, sc1);
        const float* vr = &Vs[cc * 64 + jq];
#pragma unroll
        for (int i = 0; i < 4; i++) {
            ulonglong2 t = *(const ulonglong2*)(vr + i * 4);
            at2[0][2 * i]     = ffma2(sb0, t.x, at2[0][2 * i]);
            at2[0][2 * i + 1] = ffma2(sb0, t.y, at2[0][2 * i + 1]);
            at2[1][2 * i]     = ffma2(sb1, t.x, at2[1][2 * i]);
            at2[1][2 * i + 1] = ffma2(sb1, t.y, at2[1][2 * i + 1]);
        }
    }

    // softmax over d_k (64 j split across the 4 q-lanes) + split-bf16 writeout
#pragma unroll
    for (int b = 0; b < 2; b++) {
        float e[16];
        float mx = -3.4e38f;
#pragma unroll
        for (int i = 0; i < 8; i++) {
            float lo, hi;
            upk2(lo, hi, at2[b][i]);
            e[2 * i] = lo; e[2 * i + 1] = hi;
            mx = fmaxf(mx, fmaxf(lo, hi));
        }
        mx = fmaxf(mx, __shfl_xor_sync(0xffffffffu, mx, 1));
        mx = fmaxf(mx, __shfl_xor_sync(0xffffffffu, mx, 2));
        float sum = 0.0f;
#pragma unroll
        for (int i = 0; i < 16; i++) { e[i] = __expf(e[i] - mx); sum += e[i]; }
        sum += __shfl_xor_sync(0xffffffffu, sum, 1);
        sum += __shfl_xor_sync(0xffffffffu, sum, 2);
        const float inv = 1.0f / sum;

        uint32_t hh[8], ll[8];
#pragma unroll
        for (int p = 0; p < 8; p++)
            split2(e[2 * p] * inv, e[2 * p + 1] * inv, hh[p], ll[p]);

        const int brow = bp + b * 32;
        const size_t off = head_base + (size_t)brow * DM + jq;
        *reinterpret_cast<uint4*>(Ch + off)     = make_uint4(hh[0], hh[1], hh[2], hh[3]);
        *reinterpret_cast<uint4*>(Ch + off + 8) = make_uint4(hh[4], hh[5], hh[6], hh[7]);
        *reinterpret_cast<uint4*>(Cl + off)     = make_uint4(ll[0], ll[1], ll[2], ll[3]);
        *reinterpret_cast<uint4*>(Cl + off + 8) = make_uint4(ll[4], ll[5], ll[6], ll[7]);
    }
}

extern "C" void kernel_launch(void* const* d_in, const int* in_sizes, int n_in,
                              void* d_out, int out_size) {
    const float* kin  = (const float*)d_in[0];
    const float* vin  = (const float*)d_in[1];
    const int*   mask = (const int*)  d_in[2];
    const float* gt   = (const float*)d_in[3];
    const float* Wq   = (const float*)d_in[4];
    const float* bq   = (const float*)d_in[5];
    const float* Wk   = (const float*)d_in[6];
    const float* bk   = (const float*)d_in[7];
    const float* Wv   = (const float*)d_in[8];
    const float* bv   = (const float*)d_in[9];
    const float* Wo   = (const float*)d_in[10];
    const float* bo   = (const float*)d_in[11];
    float* out = (float*)d_out;

    float *pq, *pk, *pv;
    cudaGetSymbolAddress((void**)&pq, g_q);
    cudaGetSymbolAddress((void**)&pk, g_k);
    cudaGetSymbolAddress((void**)&pv, g_v);
    __nv_bfloat16 *gth, *gtl, *kh, *kl, *vh, *vl, *ch, *cl;
    cudaGetSymbolAddress((void**)&gth, g_gth); cudaGetSymbolAddress((void**)&gtl, g_gtl);
    cudaGetSymbolAddress((void**)&kh,  g_kh);  cudaGetSymbolAddress((void**)&kl,  g_kl);
    cudaGetSymbolAddress((void**)&vh,  g_vh);  cudaGetSymbolAddress((void**)&vl,  g_vl);
    cudaGetSymbolAddress((void**)&ch,  g_ch);  cudaGetSymbolAddress((void**)&cl,  g_cl);
    __nv_bfloat16 *wqh, *wql, *wkh, *wkl, *wvh, *wvl, *woh, *wol;
    cudaGetSymbolAddress((void**)&wqh, g_wqh); cudaGetSymbolAddress((void**)&wql, g_wql);
    cudaGetSymbolAddress((void**)&wkh, g_wkh); cudaGetSymbolAddress((void**)&wkl, g_wkl);
    cudaGetSymbolAddress((void**)&wvh, g_wvh); cudaGetSymbolAddress((void**)&wvl, g_wvl);
    cudaGetSymbolAddress((void**)&woh, g_woh); cudaGetSymbolAddress((void**)&wol, g_wol);

    cudaFuncSetAttribute(gemm_tc, cudaFuncAttributeMaxDynamicSharedMemorySize, SMEM_TOTAL);
    cudaFuncSetAttribute(attn_kernel, cudaFuncAttributeMaxDynamicSharedMemorySize,
                         ATTN_SMEM_FLOATS * 4);

    const int nBig4 = MTOT * DM / 4;      // 16M float4's
    const int nW4   = DM * DM / 4;        // 256K float4's
    split_kernel<<<nBig4 / 256, 256>>>(gt,  gth, gtl, nBig4);
    split_kernel<<<nBig4 / 256, 256>>>(kin, kh,  kl,  nBig4);
    split_kernel<<<nBig4 / 256, 256>>>(vin, vh,  vl,  nBig4);
    split_kernel<<<nW4 / 256, 256>>>(Wq, wqh, wql, nW4);
    split_kernel<<<nW4 / 256, 256>>>(Wk, wkh, wkl, nW4);
    split_kernel<<<nW4 / 256, 256>>>(Wv, wvh, wvl, nW4);
    split_kernel<<<nW4 / 256, 256>>>(Wo, woh, wol, nW4);

    dim3 gg(DM / BN, MTOT / BM);   // (8, 512)
    gemm_tc<<<gg, GEMM_THREADS, SMEM_TOTAL>>>(gth, gtl, wqh, wql, bq, pq);
    gemm_tc<<<gg, GEMM_THREADS, SMEM_TOTAL>>>(kh,  kl,  wkh, wkl, bk, pk);
    gemm_tc<<<gg, GEMM_THREADS, SMEM_TOTAL>>>(vh,  vl,  wvh, wvl, bv, pv);
    attn_kernel<<<dim3(SLEN, NH), 128, ATTN_SMEM_FLOATS * 4>>>(mask, pq, pk, pv, ch, cl);
    gemm_tc<<<gg, GEMM_THREADS, SMEM_TOTAL>>>(ch, cl, woh, wol, bo, out);
}

// round 10
// speedup vs baseline: 1.4697x; 1.4697x over previous
#include <cuda_runtime.h>
#include <cuda_bf16.h>
#include <cstdint>

#define SLEN 1024
#define BSZ  64
#define DM   1024
#define NH   16
#define DK   64
#define MTOT (SLEN*BSZ)   // 65536

// GEMM tiling (warp-level HMMA)
#define BM 128
#define BN 128
#define BK 32
#define NSTAGES (DM/BK)        // 32
#define GEMM_THREADS 256

#define STAGE_BYTES 32768      // Ah 8K + Al 8K + Wh 8K + Wl 8K
#define AH_OFF 0
#define AL_OFF 8192
#define WH_OFF 16384
#define WL_OFF 24576
#define SMEM_TOTAL (2*STAGE_BYTES)   // 64KB, double buffered

// ---------------- device scratch (no allocations allowed) ----------------
__device__ float g_q[(size_t)MTOT*DM];
__device__ float g_k[(size_t)MTOT*DM];
__device__ float g_v[(size_t)MTOT*DM];
__device__ __nv_bfloat16 g_ch[(size_t)MTOT*DM];
__device__ __nv_bfloat16 g_cl[(size_t)MTOT*DM];

__device__ __nv_bfloat16 g_wqh[DM*DM], g_wql[DM*DM];
__device__ __nv_bfloat16 g_wkh[DM*DM], g_wkl[DM*DM];
__device__ __nv_bfloat16 g_wvh[DM*DM], g_wvl[DM*DM];
__device__ __nv_bfloat16 g_woh[DM*DM], g_wol[DM*DM];

typedef unsigned long long ull;

// ---------- packed fp32x2 helpers ----------
__device__ __forceinline__ ull pk2(float lo, float hi) {
    ull r;
    asm("mov.b64 %0, {%1, %2};" : "=l"(r) : "f"(lo), "f"(hi));
    return r;
}
__device__ __forceinline__ void upk2(float& lo, float& hi, ull v) {
    asm("mov.b64 {%0, %1}, %2;" : "=f"(lo), "=f"(hi) : "l"(v));
}
__device__ __forceinline__ ull ffma2(ull a, ull b, ull c) {
    ull d;
    asm("fma.rn.f32x2 %0, %1, %2, %3;" : "=l"(d) : "l"(a), "l"(b), "l"(c));
    return d;
}

// swizzled byte offset inside one GEMM tile: 64B rows, 8B chunks XORed by row&7
__device__ __forceinline__ uint32_t swz(uint32_t row, uint32_t col_elem) {
    uint32_t chunk = (col_elem >> 2) ^ (row & 7);
    return row * 64 + chunk * 8 + (col_elem & 3) * 2;
}

// truncation split: x -> hi(bf16 truncated) + lo(bf16 rn of residual)
__device__ __forceinline__ void split2(float x, float y, uint32_t& hi2, uint32_t& lo2) {
    uint32_t xb = __float_as_uint(x), yb = __float_as_uint(y);
    hi2 = __byte_perm(xb, yb, 0x7632);
    float xr = x - __uint_as_float(xb & 0xFFFF0000u);
    float yr = y - __uint_as_float(yb & 0xFFFF0000u);
    __nv_bfloat162 l = __floats2bfloat162_rn(xr, yr);
    lo2 = *reinterpret_cast<uint32_t*>(&l);
}

__device__ __forceinline__ void mma_bf16(float* d, const uint32_t* a, const uint32_t* b) {
    asm volatile(
        "mma.sync.aligned.m16n8k16.row.col.f32.bf16.bf16.f32 "
        "{%0,%1,%2,%3}, {%4,%5,%6,%7}, {%8,%9}, {%0,%1,%2,%3};"
        : "+f"(d[0]), "+f"(d[1]), "+f"(d[2]), "+f"(d[3])
        : "r"(a[0]), "r"(a[1]), "r"(a[2]), "r"(a[3]), "r"(b[0]), "r"(b[1]));
}

// ---------------- split pass (weights only; 4MB each => negligible) ----------------
__global__ __launch_bounds__(256)
void split_kernel(const float* __restrict__ X, __nv_bfloat16* __restrict__ Xh,
                  __nv_bfloat16* __restrict__ Xl, int n4) {
    int i = blockIdx.x * blockDim.x + threadIdx.x;
    if (i >= n4) return;
    float4 v = ((const float4*)X)[i];
    uint32_t h0, l0, h1, l1;
    split2(v.x, v.y, h0, l0);
    split2(v.z, v.w, h1, l1);
    ((uint2*)Xh)[i] = make_uint2(h0, h1);
    ((uint2*)Xl)[i] = make_uint2(l0, l1);
}

// ============ shared GEMM consumer (R8-proven) ============
#define GEMM_PREAMBLE \
    extern __shared__ char smem[]; \
    const int tid = threadIdx.x; \
    const int lane = tid & 31; \
    const int wid = tid >> 5; \
    const int wm = wid & 1; \
    const int wn = wid >> 1; \
    const int g = lane >> 2; \
    const int c = lane & 3; \
    const int m0 = blockIdx.y * BM; \
    const int n0 = blockIdx.x * BN; \
    const int c4 = tid & 7; \
    const int rbase = tid >> 3; \
    float acc[4][4][4]; \
    _Pragma("unroll") \
    for (int mf = 0; mf < 4; mf++) \
        _Pragma("unroll") \
        for (int nf = 0; nf < 4; nf++) \
            _Pragma("unroll") \
            for (int q = 0; q < 4; q++) acc[mf][nf][q] = 0.0f;

#define GEMM_COMPUTE_STAGE(sbuf) \
    { \
        char* sb = (sbuf); \
        char* pAh = sb + AH_OFF; char* pAl = sb + AL_OFF; \
        char* pWh = sb + WH_OFF; char* pWl = sb + WL_OFF; \
        _Pragma("unroll") \
        for (int kk = 0; kk < 2; kk++) { \
            uint32_t ah[4][4], al[4][4], bh[4][2], bl[4][2]; \
            const int colk = kk * 16 + c * 2; \
            _Pragma("unroll") \
            for (int mf = 0; mf < 4; mf++) { \
                const uint32_t r0 = wm * 64 + mf * 16 + g; \
                ah[mf][0] = *(const uint32_t*)(pAh + swz(r0,     colk)); \
                ah[mf][1] = *(const uint32_t*)(pAh + swz(r0 + 8, colk)); \
                ah[mf][2] = *(const uint32_t*)(pAh + swz(r0,     colk + 8)); \
                ah[mf][3] = *(const uint32_t*)(pAh + swz(r0 + 8, colk + 8)); \
                al[mf][0] = *(const uint32_t*)(pAl + swz(r0,     colk)); \
                al[mf][1] = *(const uint32_t*)(pAl + swz(r0 + 8, colk)); \
                al[mf][2] = *(const uint32_t*)(pAl + swz(r0,     colk + 8)); \
                al[mf][3] = *(const uint32_t*)(pAl + swz(r0 + 8, colk + 8)); \
            } \
            _Pragma("unroll") \
            for (int nf = 0; nf < 4; nf++) { \
                const uint32_t rn = wn * 32 + nf * 8 + g; \
                bh[nf][0] = *(const uint32_t*)(pWh + swz(rn, colk)); \
                bh[nf][1] = *(const uint32_t*)(pWh + swz(rn, colk + 8)); \
                bl[nf][0] = *(const uint32_t*)(pWl + swz(rn, colk)); \
                bl[nf][1] = *(const uint32_t*)(pWl + swz(rn, colk + 8)); \
            } \
            _Pragma("unroll") \
            for (int mf = 0; mf < 4; mf++) \
                _Pragma("unroll") \
                for (int nf = 0; nf < 4; nf++) { \
                    mma_bf16(acc[mf][nf], ah[mf], bh[nf]); \
                    mma_bf16(acc[mf][nf], ah[mf], bl[nf]); \
                    mma_bf16(acc[mf][nf], al[mf], bh[nf]); \
                } \
        } \
    }

#define GEMM_EPILOGUE \
    float2 bvv[4]; \
    _Pragma("unroll") \
    for (int nf = 0; nf < 4; nf++) { \
        int col = n0 + wn * 32 + nf * 8 + c * 2; \
        bvv[nf] = make_float2(bias[col], bias[col + 1]); \
    } \
    _Pragma("unroll") \
    for (int mf = 0; mf < 4; mf++) { \
        const int row = m0 + wm * 64 + mf * 16 + g; \
        _Pragma("unroll") \
        for (int nf = 0; nf < 4; nf++) { \
            const int col = n0 + wn * 32 + nf * 8 + c * 2; \
            float2 v0 = make_float2(acc[mf][nf][0] + bvv[nf].x, acc[mf][nf][1] + bvv[nf].y); \
            float2 v1 = make_float2(acc[mf][nf][2] + bvv[nf].x, acc[mf][nf][3] + bvv[nf].y); \
            *(float2*)(C + (size_t)row * DM + col) = v0; \
            *(float2*)(C + (size_t)(row + 8) * DM + col) = v1; \
        } \
    }

// ---------- GEMM variant 1: A fp32 (in-kernel split), W pre-split ----------
__global__ __launch_bounds__(GEMM_THREADS, 1)
void gemm_mixed(const float* __restrict__ A,
                const __nv_bfloat16* __restrict__ Wh, const __nv_bfloat16* __restrict__ Wl,
                const float* __restrict__ bias, float* __restrict__ C) {
    GEMM_PREAMBLE

    const float* pA[4];
    const __nv_bfloat16 *pWh[4], *pWl[4];
#pragma unroll
    for (int i = 0; i < 4; i++) {
        pA[i]  = A  + (size_t)(m0 + rbase + i * 32) * DM + c4 * 4;
        pWh[i] = Wh + (size_t)(n0 + rbase + i * 32) * DM + c4 * 4;
        pWl[i] = Wl + (size_t)(n0 + rbase + i * 32) * DM + c4 * 4;
    }

    float4 va[4]; uint2 wh[4], wl[4];
#pragma unroll
    for (int i = 0; i < 4; i++) {
        va[i] = *(const float4*)(pA[i]);
        wh[i] = *(const uint2*)(pWh[i]);
        wl[i] = *(const uint2*)(pWl[i]);
    }

    {   // store stage 0
        char* sb = smem;
#pragma unroll
        for (int i = 0; i < 4; i++) {
            uint32_t row = rbase + i * 32;
            uint32_t off = row * 64 + ((uint32_t)(c4 ^ (row & 7))) * 8;
            uint32_t h0, l0, h1, l1;
            split2(va[i].x, va[i].y, h0, l0); split2(va[i].z, va[i].w, h1, l1);
            *(uint2*)(sb + AH_OFF + off) = make_uint2(h0, h1);
            *(uint2*)(sb + AL_OFF + off) = make_uint2(l0, l1);
            *(uint2*)(sb + WH_OFF + off) = wh[i];
            *(uint2*)(sb + WL_OFF + off) = wl[i];
        }
    }
    __syncthreads();

#pragma unroll 1
    for (int s = 0; s < NSTAGES; s++) {
        if (s + 1 < NSTAGES) {
            const int k0 = (s + 1) * BK;
#pragma unroll
            for (int i = 0; i < 4; i++) {
                va[i] = *(const float4*)(pA[i] + k0);
                wh[i] = *(const uint2*)(pWh[i] + k0);
                wl[i] = *(const uint2*)(pWl[i] + k0);
            }
        }

        GEMM_COMPUTE_STAGE(smem + (s & 1) * STAGE_BYTES)

        if (s + 1 < NSTAGES) {
            char* sb = smem + ((s + 1) & 1) * STAGE_BYTES;
#pragma unroll
            for (int i = 0; i < 4; i++) {
                uint32_t row = rbase + i * 32;
                uint32_t off = row * 64 + ((uint32_t)(c4 ^ (row & 7))) * 8;
                uint32_t h0, l0, h1, l1;
                split2(va[i].x, va[i].y, h0, l0); split2(va[i].z, va[i].w, h1, l1);
                *(uint2*)(sb + AH_OFF + off) = make_uint2(h0, h1);
                *(uint2*)(sb + AL_OFF + off) = make_uint2(l0, l1);
                *(uint2*)(sb + WH_OFF + off) = wh[i];
                *(uint2*)(sb + WL_OFF + off) = wl[i];
            }
        }
        __syncthreads();
    }

    GEMM_EPILOGUE
}

// ---------- GEMM variant 2: A pre-split AND W pre-split (O projection) ----------
__global__ __launch_bounds__(GEMM_THREADS, 1)
void gemm_presplit(const __nv_bfloat16* __restrict__ Ah, const __nv_bfloat16* __restrict__ Al,
                   const __nv_bfloat16* __restrict__ Wh, const __nv_bfloat16* __restrict__ Wl,
                   const float* __restrict__ bias, float* __restrict__ C) {
    GEMM_PREAMBLE

    const __nv_bfloat16 *pAh[4], *pAl[4], *pWh[4], *pWl[4];
#pragma unroll
    for (int i = 0; i < 4; i++) {
        pAh[i] = Ah + (size_t)(m0 + rbase + i * 32) * DM + c4 * 4;
        pAl[i] = Al + (size_t)(m0 + rbase + i * 32) * DM + c4 * 4;
        pWh[i] = Wh + (size_t)(n0 + rbase + i * 32) * DM + c4 * 4;
        pWl[i] = Wl + (size_t)(n0 + rbase + i * 32) * DM + c4 * 4;
    }

    uint2 ah_[4], al_[4], wh[4], wl[4];
#pragma unroll
    for (int i = 0; i < 4; i++) {
        ah_[i] = *(const uint2*)(pAh[i]);
        al_[i] = *(const uint2*)(pAl[i]);
        wh[i]  = *(const uint2*)(pWh[i]);
        wl[i]  = *(const uint2*)(pWl[i]);
    }

    {
        char* sb = smem;
#pragma unroll
        for (int i = 0; i < 4; i++) {
            uint32_t row = rbase + i * 32;
            uint32_t off = row * 64 + ((uint32_t)(c4 ^ (row & 7))) * 8;
            *(uint2*)(sb + AH_OFF + off) = ah_[i];
            *(uint2*)(sb + AL_OFF + off) = al_[i];
            *(uint2*)(sb + WH_OFF + off) = wh[i];
            *(uint2*)(sb + WL_OFF + off) = wl[i];
        }
    }
    __syncthreads();

#pragma unroll 1
    for (int s = 0; s < NSTAGES; s++) {
        if (s + 1 < NSTAGES) {
            const int k0 = (s + 1) * BK;
#pragma unroll
            for (int i = 0; i < 4; i++) {
                ah_[i] = *(const uint2*)(pAh[i] + k0);
                al_[i] = *(const uint2*)(pAl[i] + k0);
                wh[i]  = *(const uint2*)(pWh[i] + k0);
                wl[i]  = *(const uint2*)(pWl[i] + k0);
            }
        }

        GEMM_COMPUTE_STAGE(smem + (s & 1) * STAGE_BYTES)

        if (s + 1 < NSTAGES) {
            char* sb = smem + ((s + 1) & 1) * STAGE_BYTES;
#pragma unroll
            for (int i = 0; i < 4; i++) {
                uint32_t row = rbase + i * 32;
                uint32_t off = row * 64 + ((uint32_t)(c4 ^ (row & 7))) * 8;
                *(uint2*)(sb + AH_OFF + off) = ah_[i];
                *(uint2*)(sb + AL_OFF + off) = al_[i];
                *(uint2*)(sb + WH_OFF + off) = wh[i];
                *(uint2*)(sb + WL_OFF + off) = wl[i];
            }
        }
        __syncthreads();
    }

    GEMM_EPILOGUE
}

// ---------- attention v3 (validated in R9): 2 b-rows x 16 j per thread ----------
#define KS_OFF 0
#define VS_OFF 4096
#define QS_OFF 8192
#define QS_STRIDE 68
#define ATTN_SMEM_FLOATS (QS_OFF + 64*QS_STRIDE)   // 12544 floats = 50176 B

__global__ __launch_bounds__(128)
void attn_kernel(const int* __restrict__ mask,
                 const float* __restrict__ Q, const float* __restrict__ K,
                 const float* __restrict__ V,
                 __nv_bfloat16* __restrict__ Ch, __nv_bfloat16* __restrict__ Cl) {
    extern __shared__ float sm[];
    float* Ks = sm + KS_OFF;   // [c][j], stride 64
    float* Vs = sm + VS_OFF;   // [c][j], stride 64
    float* Qs = sm + QS_OFF;   // [b][j], stride 68
    __shared__ float wred[2];

    const int s = blockIdx.x;
    const int h = blockIdx.y;
    const int tid = threadIdx.x;
    const int lane = tid & 31;
    const int w = tid >> 5;

    const size_t head_base = ((size_t)s * 64) * DM + (size_t)h * 64;

#pragma unroll 4
    for (int i = 0; i < 16; i++) {
        const int row = w * 16 + i;
        const float* gsrc = K + head_base + (size_t)row * DM + lane * 2;
        *(float2*)&Ks[row * 64 + lane * 2] = *(const float2*)gsrc;
        gsrc = V + head_base + (size_t)row * DM + lane * 2;
        *(float2*)&Vs[row * 64 + lane * 2] = *(const float2*)gsrc;
        gsrc = Q + head_base + (size_t)row * DM + lane * 2;
        *(float2*)&Qs[row * QS_STRIDE + lane * 2] = *(const float2*)gsrc;
    }

    if (tid < 64) {
        int mv = mask[tid * SLEN + s];
        float m = (float)(mv * mv);
#pragma unroll
        for (int off = 16; off; off >>= 1) m += __shfl_xor_sync(0xffffffffu, m, off);
        if (lane == 0) wred[w] = m;
    }
    __syncthreads();
    const bool masked = (wred[0] + wred[1]) == 0.0f;

    const int bp = tid >> 2;
    const int q  = tid & 3;
    const int jq = q * 16;

    ull qr2[2][8];
#pragma unroll
    for (int b = 0; b < 2; b++) {
        const float* qp = &Qs[(bp + b * 32) * QS_STRIDE + jq];
#pragma unroll
        for (int i = 0; i < 4; i++) {
            ulonglong2 t = *(const ulonglong2*)(qp + i * 4);
            qr2[b][2 * i] = t.x; qr2[b][2 * i + 1] = t.y;
        }
    }

    ull at2[2][8];
#pragma unroll
    for (int b = 0; b < 2; b++)
#pragma unroll
        for (int i = 0; i < 8; i++) at2[b][i] = 0ULL;

#pragma unroll 2
    for (int cc = 0; cc < 64; cc++) {
        const float* kr = &Ks[cc * 64 + jq];
        ull kk[8];
#pragma unroll
        for (int i = 0; i < 4; i++) {
            ulonglong2 t = *(const ulonglong2*)(kr + i * 4);
            kk[2 * i] = t.x; kk[2 * i + 1] = t.y;
        }
        ull s0 = 0ULL, s1 = 0ULL;
#pragma unroll
        for (int i = 0; i < 8; i++) {
            s0 = ffma2(qr2[0][i], kk[i], s0);
            s1 = ffma2(qr2[1][i], kk[i], s1);
        }
        float lo, hi;
        upk2(lo, hi, s0); float d0 = lo + hi;
        upk2(lo, hi, s1); float d1 = lo + hi;
        d0 += __shfl_xor_sync(0xffffffffu, d0, 1);
        d0 += __shfl_xor_sync(0xffffffffu, d0, 2);
        d1 += __shfl_xor_sync(0xffffffffu, d1, 1);
        d1 += __shfl_xor_sync(0xffffffffu, d1, 2);
        const float sc0 = masked ? -1e9f : d0 * 0.125f;
        const float sc1 = masked ? -1e9f : d1 * 0.125f;
        const ull sb0 = pk2(sc0, sc0);
        const ull sb1 = pk2(sc1, sc1);
        const float* vr = &Vs[cc * 64 + jq];
#pragma unroll
        for (int i = 0; i < 4; i++) {
            ulonglong2 t = *(const ulonglong2*)(vr + i * 4);
            at2[0][2 * i]     = ffma2(sb0, t.x, at2[0][2 * i]);
            at2[0][2 * i + 1] = ffma2(sb0, t.y, at2[0][2 * i + 1]);
            at2[1][2 * i]     = ffma2(sb1, t.x, at2[1][2 * i]);
            at2[1][2 * i + 1] = ffma2(sb1, t.y, at2[1][2 * i + 1]);
        }
    }

#pragma unroll
    for (int b = 0; b < 2; b++) {
        float e[16];
        float mx = -3.4e38f;
#pragma unroll
        for (int i = 0; i < 8; i++) {
            float lo, hi;
            upk2(lo, hi, at2[b][i]);
            e[2 * i] = lo; e[2 * i + 1] = hi;
            mx = fmaxf(mx, fmaxf(lo, hi));
        }
        mx = fmaxf(mx, __shfl_xor_sync(0xffffffffu, mx, 1));
        mx = fmaxf(mx, __shfl_xor_sync(0xffffffffu, mx, 2));
        float sum = 0.0f;
#pragma unroll
        for (int i = 0; i < 16; i++) { e[i] = __expf(e[i] - mx); sum += e[i]; }
        sum += __shfl_xor_sync(0xffffffffu, sum, 1);
        sum += __shfl_xor_sync(0xffffffffu, sum, 2);
        const float inv = 1.0f / sum;

        uint32_t hh[8], ll[8];
#pragma unroll
        for (int p = 0; p < 8; p++)
            split2(e[2 * p] * inv, e[2 * p + 1] * inv, hh[p], ll[p]);

        const int brow = bp + b * 32;
        const size_t off = head_base + (size_t)brow * DM + jq;
        *reinterpret_cast<uint4*>(Ch + off)     = make_uint4(hh[0], hh[1], hh[2], hh[3]);
        *reinterpret_cast<uint4*>(Ch + off + 8) = make_uint4(hh[4], hh[5], hh[6], hh[7]);
        *reinterpret_cast<uint4*>(Cl + off)     = make_uint4(ll[0], ll[1], ll[2], ll[3]);
        *reinterpret_cast<uint4*>(Cl + off + 8) = make_uint4(ll[4], ll[5], ll[6], ll[7]);
    }
}

extern "C" void kernel_launch(void* const* d_in, const int* in_sizes, int n_in,
                              void* d_out, int out_size) {
    const float* kin  = (const float*)d_in[0];
    const float* vin  = (const float*)d_in[1];
    const int*   mask = (const int*)  d_in[2];
    const float* gt   = (const float*)d_in[3];
    const float* Wq   = (const float*)d_in[4];
    const float* bq   = (const float*)d_in[5];
    const float* Wk   = (const float*)d_in[6];
    const float* bk   = (const float*)d_in[7];
    const float* Wv   = (const float*)d_in[8];
    const float* bv   = (const float*)d_in[9];
    const float* Wo   = (const float*)d_in[10];
    const float* bo   = (const float*)d_in[11];
    float* out = (float*)d_out;

    float *pq, *pk, *pv;
    cudaGetSymbolAddress((void**)&pq, g_q);
    cudaGetSymbolAddress((void**)&pk, g_k);
    cudaGetSymbolAddress((void**)&pv, g_v);
    __nv_bfloat16 *ch, *cl;
    cudaGetSymbolAddress((void**)&ch, g_ch);
    cudaGetSymbolAddress((void**)&cl, g_cl);
    __nv_bfloat16 *wqh, *wql, *wkh, *wkl, *wvh, *wvl, *woh, *wol;
    cudaGetSymbolAddress((void**)&wqh, g_wqh); cudaGetSymbolAddress((void**)&wql, g_wql);
    cudaGetSymbolAddress((void**)&wkh, g_wkh); cudaGetSymbolAddress((void**)&wkl, g_wkl);
    cudaGetSymbolAddress((void**)&wvh, g_wvh); cudaGetSymbolAddress((void**)&wvl, g_wvl);
    cudaGetSymbolAddress((void**)&woh, g_woh); cudaGetSymbolAddress((void**)&wol, g_wol);

    cudaFuncSetAttribute(gemm_mixed,    cudaFuncAttributeMaxDynamicSharedMemorySize, SMEM_TOTAL);
    cudaFuncSetAttribute(gemm_presplit, cudaFuncAttributeMaxDynamicSharedMemorySize, SMEM_TOTAL);
    cudaFuncSetAttribute(attn_kernel, cudaFuncAttributeMaxDynamicSharedMemorySize,
                         ATTN_SMEM_FLOATS * 4);

    const int nW4 = DM * DM / 4;   // 262144
    split_kernel<<<nW4 / 256, 256>>>(Wq, wqh, wql, nW4);
    split_kernel<<<nW4 / 256, 256>>>(Wk, wkh, wkl, nW4);
    split_kernel<<<nW4 / 256, 256>>>(Wv, wvh, wvl, nW4);
    split_kernel<<<nW4 / 256, 256>>>(Wo, woh, wol, nW4);

    dim3 gg(DM / BN, MTOT / BM);   // (8, 512)
    gemm_mixed<<<gg, GEMM_THREADS, SMEM_TOTAL>>>(gt,  wqh, wql, bq, pq);
    gemm_mixed<<<gg, GEMM_THREADS, SMEM_TOTAL>>>(kin, wkh, wkl, bk, pk);
    gemm_mixed<<<gg, GEMM_THREADS, SMEM_TOTAL>>>(vin, wvh, wvl, bv, pv);
    attn_kernel<<<dim3(SLEN, NH), 128, ATTN_SMEM_FLOATS * 4>>>(mask, pq, pk, pv, ch, cl);
    gemm_presplit<<<gg, GEMM_THREADS, SMEM_TOTAL>>>(ch, cl, woh, wol, bo, out);
}

// round 12
// speedup vs baseline: 1.7573x; 1.1957x over previous
#include <cuda_runtime.h>
#include <cuda_bf16.h>
#include <cstdint>

#define SLEN 1024
#define BSZ  64
#define DM   1024
#define NH   16
#define DK   64
#define MTOT (SLEN*BSZ)   // 65536

// GEMM tiling (warp-level HMMA)
#define BM 128
#define BN 128
#define BK 32
#define NSTAGES (DM/BK)        // 32
#define GEMM_THREADS 256

#define STAGE_BYTES 32768      // Ah 8K + Al 8K + Wh 8K + Wl 8K
#define AH_OFF 0
#define AL_OFF 8192
#define WH_OFF 16384
#define WL_OFF 24576
#define SMEM_TOTAL (2*STAGE_BYTES)   // 64KB, double buffered

// ---------------- device scratch (no allocations allowed) ----------------
__device__ float g_q[(size_t)MTOT*DM];
__device__ float g_k[(size_t)MTOT*DM];
__device__ float g_v[(size_t)MTOT*DM];
// attention output, interleaved split: one uint4 = 4 elems {hi2,hi2,lo2,lo2}
__device__ uint4 g_ci[(size_t)MTOT*DM/4];
// weights, interleaved split
__device__ uint4 g_wqi[DM*DM/4];
__device__ uint4 g_wki[DM*DM/4];
__device__ uint4 g_wvi[DM*DM/4];
__device__ uint4 g_woi[DM*DM/4];

typedef unsigned long long ull;

// ---------- packed fp32x2 helpers ----------
__device__ __forceinline__ ull pk2(float lo, float hi) {
    ull r;
    asm("mov.b64 %0, {%1, %2};" : "=l"(r) : "f"(lo), "f"(hi));
    return r;
}
__device__ __forceinline__ void upk2(float& lo, float& hi, ull v) {
    asm("mov.b64 {%0, %1}, %2;" : "=f"(lo), "=f"(hi) : "l"(v));
}
__device__ __forceinline__ ull ffma2(ull a, ull b, ull c) {
    ull d;
    asm("fma.rn.f32x2 %0, %1, %2, %3;" : "=l"(d) : "l"(a), "l"(b), "l"(c));
    return d;
}

// swizzled byte offset inside one GEMM tile: 64B rows, 8B chunks XORed by row&7
__device__ __forceinline__ uint32_t swz(uint32_t row, uint32_t col_elem) {
    uint32_t chunk = (col_elem >> 2) ^ (row & 7);
    return row * 64 + chunk * 8 + (col_elem & 3) * 2;
}

// truncation split: x -> hi(bf16 truncated) + lo(bf16 rn of residual)
__device__ __forceinline__ void split2(float x, float y, uint32_t& hi2, uint32_t& lo2) {
    uint32_t xb = __float_as_uint(x), yb = __float_as_uint(y);
    hi2 = __byte_perm(xb, yb, 0x7632);
    float xr = x - __uint_as_float(xb & 0xFFFF0000u);
    float yr = y - __uint_as_float(yb & 0xFFFF0000u);
    __nv_bfloat162 l = __floats2bfloat162_rn(xr, yr);
    lo2 = *reinterpret_cast<uint32_t*>(&l);
}

__device__ __forceinline__ void mma_bf16(float* d, const uint32_t* a, const uint32_t* b) {
    asm volatile(
        "mma.sync.aligned.m16n8k16.row.col.f32.bf16.bf16.f32 "
        "{%0,%1,%2,%3}, {%4,%5,%6,%7}, {%8,%9}, {%0,%1,%2,%3};"
        : "+f"(d[0]), "+f"(d[1]), "+f"(d[2]), "+f"(d[3])
        : "r"(a[0]), "r"(a[1]), "r"(a[2]), "r"(a[3]), "r"(b[0]), "r"(b[1]));
}

// ------------- split pass (weights only, interleaved out) -------------
__global__ __launch_bounds__(256)
void split_kernel(const float* __restrict__ X, uint4* __restrict__ Xi, int n4) {
    int i = blockIdx.x * blockDim.x + threadIdx.x;
    if (i >= n4) return;
    float4 v = ((const float4*)X)[i];
    uint32_t h0, l0, h1, l1;
    split2(v.x, v.y, h0, l0);
    split2(v.z, v.w, h1, l1);
    Xi[i] = make_uint4(h0, h1, l0, l1);
}

// ============ shared GEMM consumer (R8-proven, byte-identical) ============
#define GEMM_PREAMBLE \
    extern __shared__ char smem[]; \
    const int tid = threadIdx.x; \
    const int lane = tid & 31; \
    const int wid = tid >> 5; \
    const int wm = wid & 1; \
    const int wn = wid >> 1; \
    const int g = lane >> 2; \
    const int c = lane & 3; \
    const int m0 = blockIdx.y * BM; \
    const int n0 = blockIdx.x * BN; \
    const int c4 = tid & 7; \
    const int rbase = tid >> 3; \
    float acc[4][4][4]; \
    _Pragma("unroll") \
    for (int mf = 0; mf < 4; mf++) \
        _Pragma("unroll") \
        for (int nf = 0; nf < 4; nf++) \
            _Pragma("unroll") \
            for (int q = 0; q < 4; q++) acc[mf][nf][q] = 0.0f;

#define GEMM_COMPUTE_STAGE(sbuf) \
    { \
        char* sb = (sbuf); \
        char* pAh = sb + AH_OFF; char* pAl = sb + AL_OFF; \
        char* pWh = sb + WH_OFF; char* pWl = sb + WL_OFF; \
        _Pragma("unroll") \
        for (int kk = 0; kk < 2; kk++) { \
            uint32_t ah[4][4], al[4][4], bh[4][2], bl[4][2]; \
            const int colk = kk * 16 + c * 2; \
            _Pragma("unroll") \
            for (int mf = 0; mf < 4; mf++) { \
                const uint32_t r0 = wm * 64 + mf * 16 + g; \
                ah[mf][0] = *(const uint32_t*)(pAh + swz(r0,     colk)); \
                ah[mf][1] = *(const uint32_t*)(pAh + swz(r0 + 8, colk)); \
                ah[mf][2] = *(const uint32_t*)(pAh + swz(r0,     colk + 8)); \
                ah[mf][3] = *(const uint32_t*)(pAh + swz(r0 + 8, colk + 8)); \
                al[mf][0] = *(const uint32_t*)(pAl + swz(r0,     colk)); \
                al[mf][1] = *(const uint32_t*)(pAl + swz(r0 + 8, colk)); \
                al[mf][2] = *(const uint32_t*)(pAl + swz(r0,     colk + 8)); \
                al[mf][3] = *(const uint32_t*)(pAl + swz(r0 + 8, colk + 8)); \
            } \
            _Pragma("unroll") \
            for (int nf = 0; nf < 4; nf++) { \
                const uint32_t rn = wn * 32 + nf * 8 + g; \
                bh[nf][0] = *(const uint32_t*)(pWh + swz(rn, colk)); \
                bh[nf][1] = *(const uint32_t*)(pWh + swz(rn, colk + 8)); \
                bl[nf][0] = *(const uint32_t*)(pWl + swz(rn, colk)); \
                bl[nf][1] = *(const uint32_t*)(pWl + swz(rn, colk + 8)); \
            } \
            _Pragma("unroll") \
            for (int mf = 0; mf < 4; mf++) \
                _Pragma("unroll") \
                for (int nf = 0; nf < 4; nf++) { \
                    mma_bf16(acc[mf][nf], ah[mf], bh[nf]); \
                    mma_bf16(acc[mf][nf], ah[mf], bl[nf]); \
                    mma_bf16(acc[mf][nf], al[mf], bh[nf]); \
                } \
        } \
    }

#define GEMM_EPILOGUE \
    float2 bvv[4]; \
    _Pragma("unroll") \
    for (int nf = 0; nf < 4; nf++) { \
        int col = n0 + wn * 32 + nf * 8 + c * 2; \
        bvv[nf] = make_float2(bias[col], bias[col + 1]); \
    } \
    _Pragma("unroll") \
    for (int mf = 0; mf < 4; mf++) { \
        const int row = m0 + wm * 64 + mf * 16 + g; \
        _Pragma("unroll") \
        for (int nf = 0; nf < 4; nf++) { \
            const int col = n0 + wn * 32 + nf * 8 + c * 2; \
            float2 v0 = make_float2(acc[mf][nf][0] + bvv[nf].x, acc[mf][nf][1] + bvv[nf].y); \
            float2 v1 = make_float2(acc[mf][nf][2] + bvv[nf].x, acc[mf][nf][3] + bvv[nf].y); \
            *(float2*)(C + (size_t)row * DM + col) = v0; \
            *(float2*)(C + (size_t)(row + 8) * DM + col) = v1; \
        } \
    }

// ---------- GEMM v1: A fp32 (in-kernel split), W interleaved pre-split ----------
__global__ __launch_bounds__(GEMM_THREADS, 1)
void gemm_mixed(const float* __restrict__ A, const uint4* __restrict__ Wi,
                const float* __restrict__ bias, float* __restrict__ C) {
    GEMM_PREAMBLE

    const float* pA[4];
    const uint4* pW[4];
#pragma unroll
    for (int i = 0; i < 4; i++) {
        pA[i] = A  + (size_t)(m0 + rbase + i * 32) * DM + c4 * 4;
        pW[i] = Wi + (size_t)(n0 + rbase + i * 32) * (DM / 4) + c4;
    }

    float4 va[4]; uint4 w4[4];
#pragma unroll
    for (int i = 0; i < 4; i++) { va[i] = *(const float4*)(pA[i]); w4[i] = pW[i][0]; }

    {   // store stage 0
        char* sb = smem;
#pragma unroll
        for (int i = 0; i < 4; i++) {
            uint32_t row = rbase + i * 32;
            uint32_t off = row * 64 + ((uint32_t)(c4 ^ (row & 7))) * 8;
            uint32_t h0, l0, h1, l1;
            split2(va[i].x, va[i].y, h0, l0); split2(va[i].z, va[i].w, h1, l1);
            *(uint2*)(sb + AH_OFF + off) = make_uint2(h0, h1);
            *(uint2*)(sb + AL_OFF + off) = make_uint2(l0, l1);
            *(uint2*)(sb + WH_OFF + off) = make_uint2(w4[i].x, w4[i].y);
            *(uint2*)(sb + WL_OFF + off) = make_uint2(w4[i].z, w4[i].w);
        }
    }
    __syncthreads();

#pragma unroll 1
    for (int s = 0; s < NSTAGES; s++) {
        if (s + 1 < NSTAGES) {
            const int k0 = (s + 1) * BK;
#pragma unroll
            for (int i = 0; i < 4; i++) {
                va[i] = *(const float4*)(pA[i] + k0);
                w4[i] = pW[i][k0 / 4];
            }
        }

        GEMM_COMPUTE_STAGE(smem + (s & 1) * STAGE_BYTES)

        if (s + 1 < NSTAGES) {
            char* sb = smem + ((s + 1) & 1) * STAGE_BYTES;
#pragma unroll
            for (int i = 0; i < 4; i++) {
                uint32_t row = rbase + i * 32;
                uint32_t off = row * 64 + ((uint32_t)(c4 ^ (row & 7))) * 8;
                uint32_t h0, l0, h1, l1;
                split2(va[i].x, va[i].y, h0, l0); split2(va[i].z, va[i].w, h1, l1);
                *(uint2*)(sb + AH_OFF + off) = make_uint2(h0, h1);
                *(uint2*)(sb + AL_OFF + off) = make_uint2(l0, l1);
                *(uint2*)(sb + WH_OFF + off) = make_uint2(w4[i].x, w4[i].y);
                *(uint2*)(sb + WL_OFF + off) = make_uint2(w4[i].z, w4[i].w);
            }
        }
        __syncthreads();
    }

    GEMM_EPILOGUE
}

// ---------- GEMM v2: A and W both interleaved pre-split (O projection) ----------
__global__ __launch_bounds__(GEMM_THREADS, 1)
void gemm_presplit(const uint4* __restrict__ Ai, const uint4* __restrict__ Wi,
                   const float* __restrict__ bias, float* __restrict__ C) {
    GEMM_PREAMBLE

    const uint4 *pA[4], *pW[4];
#pragma unroll
    for (int i = 0; i < 4; i++) {
        pA[i] = Ai + (size_t)(m0 + rbase + i * 32) * (DM / 4) + c4;
        pW[i] = Wi + (size_t)(n0 + rbase + i * 32) * (DM / 4) + c4;
    }

    uint4 a4[4], w4[4];
#pragma unroll
    for (int i = 0; i < 4; i++) { a4[i] = pA[i][0]; w4[i] = pW[i][0]; }

    {
        char* sb = smem;
#pragma unroll
        for (int i = 0; i < 4; i++) {
            uint32_t row = rbase + i * 32;
            uint32_t off = row * 64 + ((uint32_t)(c4 ^ (row & 7))) * 8;
            *(uint2*)(sb + AH_OFF + off) = make_uint2(a4[i].x, a4[i].y);
            *(uint2*)(sb + AL_OFF + off) = make_uint2(a4[i].z, a4[i].w);
            *(uint2*)(sb + WH_OFF + off) = make_uint2(w4[i].x, w4[i].y);
            *(uint2*)(sb + WL_OFF + off) = make_uint2(w4[i].z, w4[i].w);
        }
    }
    __syncthreads();

#pragma unroll 1
    for (int s = 0; s < NSTAGES; s++) {
        if (s + 1 < NSTAGES) {
            const int k4 = (s + 1) * BK / 4;
#pragma unroll
            for (int i = 0; i < 4; i++) { a4[i] = pA[i][k4]; w4[i] = pW[i][k4]; }
        }

        GEMM_COMPUTE_STAGE(smem + (s & 1) * STAGE_BYTES)

        if (s + 1 < NSTAGES) {
            char* sb = smem + ((s + 1) & 1) * STAGE_BYTES;
#pragma unroll
            for (int i = 0; i < 4; i++) {
                uint32_t row = rbase + i * 32;
                uint32_t off = row * 64 + ((uint32_t)(c4 ^ (row & 7))) * 8;
                *(uint2*)(sb + AH_OFF + off) = make_uint2(a4[i].x, a4[i].y);
                *(uint2*)(sb + AL_OFF + off) = make_uint2(a4[i].z, a4[i].w);
                *(uint2*)(sb + WH_OFF + off) = make_uint2(w4[i].x, w4[i].y);
                *(uint2*)(sb + WL_OFF + off) = make_uint2(w4[i].z, w4[i].w);
            }
        }
        __syncthreads();
    }

    GEMM_EPILOGUE
}

// ---------- attention v2.1 (R8-validated) + interleaved split writeout ----------
// Block = (s,h), 128 threads. Thread t: b = t>>1, half = t&1.
// j-sets: half0: [0,16)u[32,48); half1: [16,32)u[48,64)
// smem (floats): Ks[64][64] @0, Vs[64][64] @4096, Qs[64][66] @8192,
//                Stq (uint4[64][17]) @12416
#define KS_OFF 0
#define VS_OFF 4096
#define QS_OFF 8192
#define QS_STRIDE 66
#define ST_OFF (QS_OFF + 64*QS_STRIDE)               // 12416 floats (16B aligned)
#define ATTN_SMEM_FLOATS (ST_OFF + 64*17*4)          // + 4352 = 16768 floats = 67072 B

__global__ __launch_bounds__(128)
void attn_kernel(const int* __restrict__ mask,
                 const float* __restrict__ Q, const float* __restrict__ K,
                 const float* __restrict__ V, uint4* __restrict__ Ci) {
    extern __shared__ float sm[];
    float* Ks = sm + KS_OFF;   // [c][j], stride 64
    float* Vs = sm + VS_OFF;   // [c][j], stride 64
    float* Qs = sm + QS_OFF;   // [b][j], stride 66
    uint4* Stq = (uint4*)(sm + ST_OFF);   // [b][17]
    __shared__ float wred[2];

    const int s = blockIdx.x;
    const int h = blockIdx.y;
    const int tid = threadIdx.x;
    const int lane = tid & 31;
    const int w = tid >> 5;

    const size_t head_base = ((size_t)s * 64) * DM + (size_t)h * 64;

    // coalesced loads: warp w handles rows [w*16, w*16+16)
#pragma unroll 4
    for (int i = 0; i < 16; i++) {
        const int row = w * 16 + i;
        const float* gsrc = K + head_base + (size_t)row * DM + lane * 2;
        *(float2*)&Ks[row * 64 + lane * 2] = *(const float2*)gsrc;
        gsrc = V + head_base + (size_t)row * DM + lane * 2;
        *(float2*)&Vs[row * 64 + lane * 2] = *(const float2*)gsrc;
        gsrc = Q + head_base + (size_t)row * DM + lane * 2;
        *(float2*)&Qs[row * QS_STRIDE + lane * 2] = *(const float2*)gsrc;
    }

    if (tid < 64) {
        int mv = mask[tid * SLEN + s];
        float m = (float)(mv * mv);
#pragma unroll
        for (int off = 16; off; off >>= 1) m += __shfl_xor_sync(0xffffffffu, m, off);
        if (lane == 0) wred[w] = m;
    }
    __syncthreads();
    const bool masked = (wred[0] + wred[1]) == 0.0f;

    const int b = tid >> 1;
    const int half = tid & 1;
    const int jb0 = half * 16;
    const int jb1 = 32 + half * 16;

    // load this thread's q slice (one-time scalar LDS, <=2-way conflicts)
    ull qr2[16];
#pragma unroll
    for (int i = 0; i < 8; i++) {
        qr2[i]     = pk2(Qs[b * QS_STRIDE + jb0 + 2 * i], Qs[b * QS_STRIDE + jb0 + 2 * i + 1]);
        qr2[8 + i] = pk2(Qs[b * QS_STRIDE + jb1 + 2 * i], Qs[b * QS_STRIDE + jb1 + 2 * i + 1]);
    }

    ull at2[16];
#pragma unroll
    for (int i = 0; i < 16; i++) at2[i] = 0ULL;

#pragma unroll 1
    for (int cg = 0; cg < 8; cg++) {
        ull sc2[8];
#pragma unroll
        for (int i = 0; i < 8; i++) sc2[i] = 0ULL;
#pragma unroll
        for (int cc = 0; cc < 8; cc++) {
            const int c = cg * 8 + cc;
            const ulonglong2* kp0 = (const ulonglong2*)&Ks[c * 64 + jb0];
            const ulonglong2* kp1 = (const ulonglong2*)&Ks[c * 64 + jb1];
#pragma unroll
            for (int i = 0; i < 4; i++) {
                ulonglong2 k4 = kp0[i];
                sc2[cc] = ffma2(qr2[2 * i], k4.x, sc2[cc]);
                sc2[cc] = ffma2(qr2[2 * i + 1], k4.y, sc2[cc]);
                ulonglong2 k5 = kp1[i];
                sc2[cc] = ffma2(qr2[8 + 2 * i], k5.x, sc2[cc]);
                sc2[cc] = ffma2(qr2[8 + 2 * i + 1], k5.y, sc2[cc]);
            }
        }
        float sc[8];
#pragma unroll
        for (int cc = 0; cc < 8; cc++) {
            float lo, hi;
            upk2(lo, hi, sc2[cc]);
            float sv = lo + hi;
            sv += __shfl_xor_sync(0xffffffffu, sv, 1);   // partner half of the dot
            sc[cc] = masked ? -1e9f : sv * 0.125f;
        }
#pragma unroll
        for (int cc = 0; cc < 8; cc++) {
            const int c = cg * 8 + cc;
            const ull sb2 = pk2(sc[cc], sc[cc]);
            const ulonglong2* vp0 = (const ulonglong2*)&Vs[c * 64 + jb0];
            const ulonglong2* vp1 = (const ulonglong2*)&Vs[c * 64 + jb1];
#pragma unroll
            for (int i = 0; i < 4; i++) {
                ulonglong2 v4 = vp0[i];
                at2[2 * i]     = ffma2(sb2, v4.x, at2[2 * i]);
                at2[2 * i + 1] = ffma2(sb2, v4.y, at2[2 * i + 1]);
                ulonglong2 v5 = vp1[i];
                at2[8 + 2 * i]     = ffma2(sb2, v5.x, at2[8 + 2 * i]);
                at2[8 + 2 * i + 1] = ffma2(sb2, v5.y, at2[8 + 2 * i + 1]);
            }
        }
    }

    // softmax over d_k (all 64 j, split across lane pair)
    float e[32];
    float mx = -3.4e38f;
#pragma unroll
    for (int i = 0; i < 16; i++) {
        float lo, hi;
        upk2(lo, hi, at2[i]);
        e[2 * i] = lo; e[2 * i + 1] = hi;
        mx = fmaxf(mx, fmaxf(lo, hi));
    }
    mx = fmaxf(mx, __shfl_xor_sync(0xffffffffu, mx, 1));
    float sum = 0.0f;
#pragma unroll
    for (int i = 0; i < 32; i++) { e[i] = __expf(e[i] - mx); sum += e[i]; }
    sum += __shfl_xor_sync(0xffffffffu, sum, 1);
    const float inv = 1.0f / sum;

    // split to interleaved bf16 chunks, stage in smem
#pragma unroll
    for (int r = 0; r < 4; r++) {
        uint32_t h0, l0, h1, l1;
        split2(e[4 * r] * inv, e[4 * r + 1] * inv, h0, l0);
        split2(e[4 * r + 2] * inv, e[4 * r + 3] * inv, h1, l1);
        Stq[b * 17 + (jb0 >> 2) + r] = make_uint4(h0, h1, l0, l1);
        split2(e[16 + 4 * r] * inv, e[16 + 4 * r + 1] * inv, h0, l0);
        split2(e[16 + 4 * r + 2] * inv, e[16 + 4 * r + 3] * inv, h1, l1);
        Stq[b * 17 + (jb1 >> 2) + r] = make_uint4(h0, h1, l0, l1);
    }
    __syncthreads();

    // coalesced writeout: 1024 uint4 chunks, 16 per row
    uint4* dst = Ci + head_base / 4;
#pragma unroll 4
    for (int t = tid; t < 1024; t += 128) {
        const int row = t >> 4, ch = t & 15;
        dst[(size_t)row * (DM / 4) + ch] = Stq[row * 17 + ch];
    }
}

extern "C" void kernel_launch(void* const* d_in, const int* in_sizes, int n_in,
                              void* d_out, int out_size) {
    const float* kin  = (const float*)d_in[0];
    const float* vin  = (const float*)d_in[1];
    const int*   mask = (const int*)  d_in[2];
    const float* gt   = (const float*)d_in[3];
    const float* Wq   = (const float*)d_in[4];
    const float* bq   = (const float*)d_in[5];
    const float* Wk   = (const float*)d_in[6];
    const float* bk   = (const float*)d_in[7];
    const float* Wv   = (const float*)d_in[8];
    const float* bv   = (const float*)d_in[9];
    const float* Wo   = (const float*)d_in[10];
    const float* bo   = (const float*)d_in[11];
    float* out = (float*)d_out;

    float *pq, *pk, *pv;
    cudaGetSymbolAddress((void**)&pq, g_q);
    cudaGetSymbolAddress((void**)&pk, g_k);
    cudaGetSymbolAddress((void**)&pv, g_v);
    uint4 *ci, *wqi, *wki, *wvi, *woi;
    cudaGetSymbolAddress((void**)&ci,  g_ci);
    cudaGetSymbolAddress((void**)&wqi, g_wqi);
    cudaGetSymbolAddress((void**)&wki, g_wki);
    cudaGetSymbolAddress((void**)&wvi, g_wvi);
    cudaGetSymbolAddress((void**)&woi, g_woi);

    cudaFuncSetAttribute(gemm_mixed,    cudaFuncAttributeMaxDynamicSharedMemorySize, SMEM_TOTAL);
    cudaFuncSetAttribute(gemm_presplit, cudaFuncAttributeMaxDynamicSharedMemorySize, SMEM_TOTAL);
    cudaFuncSetAttribute(attn_kernel, cudaFuncAttributeMaxDynamicSharedMemorySize,
                         ATTN_SMEM_FLOATS * 4);

    const int nW4 = DM * DM / 4;   // 262144
    split_kernel<<<nW4 / 256, 256>>>(Wq, wqi, nW4);
    split_kernel<<<nW4 / 256, 256>>>(Wk, wki, nW4);
    split_kernel<<<nW4 / 256, 256>>>(Wv, wvi, nW4);
    split_kernel<<<nW4 / 256, 256>>>(Wo, woi, nW4);

    dim3 gg(DM / BN, MTOT / BM);   // (8, 512)
    gemm_mixed<<<gg, GEMM_THREADS, SMEM_TOTAL>>>(gt,  wqi, bq, pq);
    gemm_mixed<<<gg, GEMM_THREADS, SMEM_TOTAL>>>(kin, wki, bk, pk);
    gemm_mixed<<<gg, GEMM_THREADS, SMEM_TOTAL>>>(vin, wvi, bv, pv);
    attn_kernel<<<dim3(SLEN, NH), 128, ATTN_SMEM_FLOATS * 4>>>(mask, pq, pk, pv, ci);
    gemm_presplit<<<gg, GEMM_THREADS, SMEM_TOTAL>>>(ci, woi, bo, out);
}

// round 16
// speedup vs baseline: 1.8873x; 1.0740x over previous
#include <cuda_runtime.h>
#include <cuda_bf16.h>
#include <cstdint>

#define SLEN 1024
#define BSZ  64
#define DM   1024
#define NH   16
#define DK   64
#define MTOT (SLEN*BSZ)   // 65536

// GEMM tiling (warp-level HMMA)
#define BM 128
#define BN 128
#define BK 32
#define NSTAGES (DM/BK)        // 32
#define GEMM_THREADS 256

#define STAGE_BYTES 32768      // Ah 8K + Al 8K + Wh 8K + Wl 8K
#define AH_OFF 0
#define AL_OFF 8192
#define WH_OFF 16384
#define WL_OFF 24576
#define SMEM_TOTAL (2*STAGE_BYTES)   // 64KB, double buffered

// ---------------- device scratch (no allocations allowed) ----------------
__device__ float g_q[(size_t)MTOT*DM];
__device__ float g_k[(size_t)MTOT*DM];
__device__ float g_v[(size_t)MTOT*DM];
// attention output, interleaved split: one uint4 = 4 elems {hi2,hi2,lo2,lo2}
__device__ uint4 g_ci[(size_t)MTOT*DM/4];
// weights, interleaved split
__device__ uint4 g_wqi[DM*DM/4];
__device__ uint4 g_wki[DM*DM/4];
__device__ uint4 g_wvi[DM*DM/4];
__device__ uint4 g_woi[DM*DM/4];

typedef unsigned long long ull;

// ---------- packed fp32x2 helpers ----------
__device__ __forceinline__ ull pk2(float lo, float hi) {
    ull r;
    asm("mov.b64 %0, {%1, %2};" : "=l"(r) : "f"(lo), "f"(hi));
    return r;
}
__device__ __forceinline__ void upk2(float& lo, float& hi, ull v) {
    asm("mov.b64 {%0, %1}, %2;" : "=f"(lo), "=f"(hi) : "l"(v));
}
__device__ __forceinline__ ull ffma2(ull a, ull b, ull c) {
    ull d;
    asm("fma.rn.f32x2 %0, %1, %2, %3;" : "=l"(d) : "l"(a), "l"(b), "l"(c));
    return d;
}

// swizzled byte offset inside one GEMM tile: 64B rows, 8B chunks XORed by row&7
__device__ __forceinline__ uint32_t swz(uint32_t row, uint32_t col_elem) {
    uint32_t chunk = (col_elem >> 2) ^ (row & 7);
    return row * 64 + chunk * 8 + (col_elem & 3) * 2;
}

// truncation split: x -> hi(bf16 truncated) + lo(bf16 rn of residual)
__device__ __forceinline__ void split2(float x, float y, uint32_t& hi2, uint32_t& lo2) {
    uint32_t xb = __float_as_uint(x), yb = __float_as_uint(y);
    hi2 = __byte_perm(xb, yb, 0x7632);
    float xr = x - __uint_as_float(xb & 0xFFFF0000u);
    float yr = y - __uint_as_float(yb & 0xFFFF0000u);
    __nv_bfloat162 l = __floats2bfloat162_rn(xr, yr);
    lo2 = *reinterpret_cast<uint32_t*>(&l);
}

__device__ __forceinline__ void mma_bf16(float* d, const uint32_t* a, const uint32_t* b) {
    asm volatile(
        "mma.sync.aligned.m16n8k16.row.col.f32.bf16.bf16.f32 "
        "{%0,%1,%2,%3}, {%4,%5,%6,%7}, {%8,%9}, {%0,%1,%2,%3};"
        : "+f"(d[0]), "+f"(d[1]), "+f"(d[2]), "+f"(d[3])
        : "r"(a[0]), "r"(a[1]), "r"(a[2]), "r"(a[3]), "r"(b[0]), "r"(b[1]));
}

// ------------- split pass (weights only, interleaved out) -------------
__global__ __launch_bounds__(256)
void split_kernel(const float* __restrict__ X, uint4* __restrict__ Xi, int n4) {
    int i = blockIdx.x * blockDim.x + threadIdx.x;
    if (i >= n4) return;
    float4 v = ((const float4*)X)[i];
    uint32_t h0, l0, h1, l1;
    split2(v.x, v.y, h0, l0);
    split2(v.z, v.w, h1, l1);
    Xi[i] = make_uint4(h0, h1, l0, l1);
}

// ============ shared GEMM consumer (R8-proven, byte-identical) ============
#define GEMM_PREAMBLE \
    extern __shared__ char smem[]; \
    const int tid = threadIdx.x; \
    const int lane = tid & 31; \
    const int wid = tid >> 5; \
    const int wm = wid & 1; \
    const int wn = wid >> 1; \
    const int g = lane >> 2; \
    const int c = lane & 3; \
    const int m0 = blockIdx.y * BM; \
    const int n0 = blockIdx.x * BN; \
    const int c4 = tid & 7; \
    const int rbase = tid >> 3; \
    float acc[4][4][4]; \
    _Pragma("unroll") \
    for (int mf = 0; mf < 4; mf++) \
        _Pragma("unroll") \
        for (int nf = 0; nf < 4; nf++) \
            _Pragma("unroll") \
            for (int q = 0; q < 4; q++) acc[mf][nf][q] = 0.0f;

#define GEMM_COMPUTE_STAGE(sbuf) \
    { \
        char* sb = (sbuf); \
        char* pAh = sb + AH_OFF; char* pAl = sb + AL_OFF; \
        char* pWh = sb + WH_OFF; char* pWl = sb + WL_OFF; \
        _Pragma("unroll") \
        for (int kk = 0; kk < 2; kk++) { \
            uint32_t ah[4][4], al[4][4], bh[4][2], bl[4][2]; \
            const int colk = kk * 16 + c * 2; \
            _Pragma("unroll") \
            for (int mf = 0; mf < 4; mf++) { \
                const uint32_t r0 = wm * 64 + mf * 16 + g; \
                ah[mf][0] = *(const uint32_t*)(pAh + swz(r0,     colk)); \
                ah[mf][1] = *(const uint32_t*)(pAh + swz(r0 + 8, colk)); \
                ah[mf][2] = *(const uint32_t*)(pAh + swz(r0,     colk + 8)); \
                ah[mf][3] = *(const uint32_t*)(pAh + swz(r0 + 8, colk + 8)); \
                al[mf][0] = *(const uint32_t*)(pAl + swz(r0,     colk)); \
                al[mf][1] = *(const uint32_t*)(pAl + swz(r0 + 8, colk)); \
                al[mf][2] = *(const uint32_t*)(pAl + swz(r0,     colk + 8)); \
                al[mf][3] = *(const uint32_t*)(pAl + swz(r0 + 8, colk + 8)); \
            } \
            _Pragma("unroll") \
            for (int nf = 0; nf < 4; nf++) { \
                const uint32_t rn = wn * 32 + nf * 8 + g; \
                bh[nf][0] = *(const uint32_t*)(pWh + swz(rn, colk)); \
                bh[nf][1] = *(const uint32_t*)(pWh + swz(rn, colk + 8)); \
                bl[nf][0] = *(const uint32_t*)(pWl + swz(rn, colk)); \
                bl[nf][1] = *(const uint32_t*)(pWl + swz(rn, colk + 8)); \
            } \
            _Pragma("unroll") \
            for (int mf = 0; mf < 4; mf++) \
                _Pragma("unroll") \
                for (int nf = 0; nf < 4; nf++) { \
                    mma_bf16(acc[mf][nf], ah[mf], bh[nf]); \
                    mma_bf16(acc[mf][nf], ah[mf], bl[nf]); \
                    mma_bf16(acc[mf][nf], al[mf], bh[nf]); \
                } \
        } \
    }

#define GEMM_EPILOGUE \
    float2 bvv[4]; \
    _Pragma("unroll") \
    for (int nf = 0; nf < 4; nf++) { \
        int col = n0 + wn * 32 + nf * 8 + c * 2; \
        bvv[nf] = make_float2(bias[col], bias[col + 1]); \
    } \
    _Pragma("unroll") \
    for (int mf = 0; mf < 4; mf++) { \
        const int row = m0 + wm * 64 + mf * 16 + g; \
        _Pragma("unroll") \
        for (int nf = 0; nf < 4; nf++) { \
            const int col = n0 + wn * 32 + nf * 8 + c * 2; \
            float2 v0 = make_float2(acc[mf][nf][0] + bvv[nf].x, acc[mf][nf][1] + bvv[nf].y); \
            float2 v1 = make_float2(acc[mf][nf][2] + bvv[nf].x, acc[mf][nf][3] + bvv[nf].y); \
            *(float2*)(C + (size_t)row * DM + col) = v0; \
            *(float2*)(C + (size_t)(row + 8) * DM + col) = v1; \
        } \
    }

// ---------- GEMM v1: A fp32 (in-kernel split), W interleaved pre-split ----------
__global__ __launch_bounds__(GEMM_THREADS, 1)
void gemm_mixed(const float* __restrict__ A, const uint4* __restrict__ Wi,
                const float* __restrict__ bias, float* __restrict__ C) {
    GEMM_PREAMBLE

    const float* pA[4];
    const uint4* pW[4];
#pragma unroll
    for (int i = 0; i < 4; i++) {
        pA[i] = A  + (size_t)(m0 + rbase + i * 32) * DM + c4 * 4;
        pW[i] = Wi + (size_t)(n0 + rbase + i * 32) * (DM / 4) + c4;
    }

    float4 va[4]; uint4 w4[4];
#pragma unroll
    for (int i = 0; i < 4; i++) { va[i] = *(const float4*)(pA[i]); w4[i] = pW[i][0]; }

    {   // store stage 0
        char* sb = smem;
#pragma unroll
        for (int i = 0; i < 4; i++) {
            uint32_t row = rbase + i * 32;
            uint32_t off = row * 64 + ((uint32_t)(c4 ^ (row & 7))) * 8;
            uint32_t h0, l0, h1, l1;
            split2(va[i].x, va[i].y, h0, l0); split2(va[i].z, va[i].w, h1, l1);
            *(uint2*)(sb + AH_OFF + off) = make_uint2(h0, h1);
            *(uint2*)(sb + AL_OFF + off) = make_uint2(l0, l1);
            *(uint2*)(sb + WH_OFF + off) = make_uint2(w4[i].x, w4[i].y);
            *(uint2*)(sb + WL_OFF + off) = make_uint2(w4[i].z, w4[i].w);
        }
    }
    __syncthreads();

#pragma unroll 1
    for (int s = 0; s < NSTAGES; s++) {
        if (s + 1 < NSTAGES) {
            const int k0 = (s + 1) * BK;
#pragma unroll
            for (int i = 0; i < 4; i++) {
                va[i] = *(const float4*)(pA[i] + k0);
                w4[i] = pW[i][k0 / 4];
            }
        }

        GEMM_COMPUTE_STAGE(smem + (s & 1) * STAGE_BYTES)

        if (s + 1 < NSTAGES) {
            char* sb = smem + ((s + 1) & 1) * STAGE_BYTES;
#pragma unroll
            for (int i = 0; i < 4; i++) {
                uint32_t row = rbase + i * 32;
                uint32_t off = row * 64 + ((uint32_t)(c4 ^ (row & 7))) * 8;
                uint32_t h0, l0, h1, l1;
                split2(va[i].x, va[i].y, h0, l0); split2(va[i].z, va[i].w, h1, l1);
                *(uint2*)(sb + AH_OFF + off) = make_uint2(h0, h1);
                *(uint2*)(sb + AL_OFF + off) = make_uint2(l0, l1);
                *(uint2*)(sb + WH_OFF + off) = make_uint2(w4[i].x, w4[i].y);
                *(uint2*)(sb + WL_OFF + off) = make_uint2(w4[i].z, w4[i].w);
            }
        }
        __syncthreads();
    }

    GEMM_EPILOGUE
}

// ---------- GEMM v2: A and W both interleaved pre-split (O projection) ----------
__global__ __launch_bounds__(GEMM_THREADS, 1)
void gemm_presplit(const uint4* __restrict__ Ai, const uint4* __restrict__ Wi,
                   const float* __restrict__ bias, float* __restrict__ C) {
    GEMM_PREAMBLE

    const uint4 *pA[4], *pW[4];
#pragma unroll
    for (int i = 0; i < 4; i++) {
        pA[i] = Ai + (size_t)(m0 + rbase + i * 32) * (DM / 4) + c4;
        pW[i] = Wi + (size_t)(n0 + rbase + i * 32) * (DM / 4) + c4;
    }

    uint4 a4[4], w4[4];
#pragma unroll
    for (int i = 0; i < 4; i++) { a4[i] = pA[i][0]; w4[i] = pW[i][0]; }

    {
        char* sb = smem;
#pragma unroll
        for (int i = 0; i < 4; i++) {
            uint32_t row = rbase + i * 32;
            uint32_t off = row * 64 + ((uint32_t)(c4 ^ (row & 7))) * 8;
            *(uint2*)(sb + AH_OFF + off) = make_uint2(a4[i].x, a4[i].y);
            *(uint2*)(sb + AL_OFF + off) = make_uint2(a4[i].z, a4[i].w);
            *(uint2*)(sb + WH_OFF + off) = make_uint2(w4[i].x, w4[i].y);
            *(uint2*)(sb + WL_OFF + off) = make_uint2(w4[i].z, w4[i].w);
        }
    }
    __syncthreads();

#pragma unroll 1
    for (int s = 0; s < NSTAGES; s++) {
        if (s + 1 < NSTAGES) {
            const int k4 = (s + 1) * BK / 4;
#pragma unroll
            for (int i = 0; i < 4; i++) { a4[i] = pA[i][k4]; w4[i] = pW[i][k4]; }
        }

        GEMM_COMPUTE_STAGE(smem + (s & 1) * STAGE_BYTES)

        if (s + 1 < NSTAGES) {
            char* sb = smem + ((s + 1) & 1) * STAGE_BYTES;
#pragma unroll
            for (int i = 0; i < 4; i++) {
                uint32_t row = rbase + i * 32;
                uint32_t off = row * 64 + ((uint32_t)(c4 ^ (row & 7))) * 8;
                *(uint2*)(sb + AH_OFF + off) = make_uint2(a4[i].x, a4[i].y);
                *(uint2*)(sb + AL_OFF + off) = make_uint2(a4[i].z, a4[i].w);
                *(uint2*)(sb + WH_OFF + off) = make_uint2(w4[i].x, w4[i].y);
                *(uint2*)(sb + WL_OFF + off) = make_uint2(w4[i].z, w4[i].w);
            }
        }
        __syncthreads();
    }

    GEMM_EPILOGUE
}

// ================== attention v4: HMMA split-bf16 ==================
// Block (s,h), 128 threads, 4 warps; warp w owns score rows b in [16w,16w+16).
// S = QK^T/8 (masked), O = S V, softmax over j of O, interleaved-split out.
// bf16x2 planes: row stride PW=36 words (144B) -> every fragment LDS.32 is
// conflict-free (bank = 4g+c+8kt, bijective over the warp).
#define PW 36
#define AQH_OFF 0
#define AQL_OFF 9216
#define AKH_OFF 18432
#define AKL_OFF 27648
#define AVS_OFF 36864                      // fp32 V, stride 68 floats
#define ATTN_SMEM_BYTES (36864 + 64*68*4)  // 54272
// overlays (after phase boundaries):
#define VTH_OFF AQH_OFF
#define VTL_OFF AQL_OFF
#define STH_OFF AKH_OFF
#define STL_OFF AKL_OFF

__global__ __launch_bounds__(128, 4)
void attn_kernel(const int* __restrict__ mask,
                 const float* __restrict__ Q, const float* __restrict__ K,
                 const float* __restrict__ V, uint4* __restrict__ Ci) {
    extern __shared__ char smraw[];
    uint32_t* QH = (uint32_t*)(smraw + AQH_OFF);
    uint32_t* QL = (uint32_t*)(smraw + AQL_OFF);
    uint32_t* KH = (uint32_t*)(smraw + AKH_OFF);
    uint32_t* KL = (uint32_t*)(smraw + AKL_OFF);
    float*    VS = (float*)   (smraw + AVS_OFF);
    uint32_t* VTH = (uint32_t*)(smraw + VTH_OFF);
    uint32_t* VTL = (uint32_t*)(smraw + VTL_OFF);
    uint32_t* SH = (uint32_t*)(smraw + STH_OFF);
    uint32_t* SL = (uint32_t*)(smraw + STL_OFF);
    __shared__ float wred[2];

    const int s = blockIdx.x;
    const int h = blockIdx.y;
    const int tid = threadIdx.x;
    const int lane = tid & 31;
    const int w = tid >> 5;
    const int g = lane >> 2;
    const int c = lane & 3;

    const size_t head_base = ((size_t)s * 64) * DM + (size_t)h * 64;

    // ---- fill: Q,K split to planes; V raw fp32 (coalesced, proven pattern) ----
#pragma unroll 4
    for (int i = 0; i < 16; i++) {
        const int row = w * 16 + i;
        float2 t = *(const float2*)(Q + head_base + (size_t)row * DM + lane * 2);
        uint32_t h2, l2;
        split2(t.x, t.y, h2, l2);
        QH[row * PW + lane] = h2;  QL[row * PW + lane] = l2;
        t = *(const float2*)(K + head_base + (size_t)row * DM + lane * 2);
        split2(t.x, t.y, h2, l2);
        KH[row * PW + lane] = h2;  KL[row * PW + lane] = l2;
        t = *(const float2*)(V + head_base + (size_t)row * DM + lane * 2);
        *(float2*)&VS[row * 68 + lane * 2] = t;
    }

    if (tid < 64) {
        int mv = mask[tid * SLEN + s];
        float m = (float)(mv * mv);
#pragma unroll
        for (int off = 16; off; off >>= 1) m += __shfl_xor_sync(0xffffffffu, m, off);
        if (lane == 0) wred[w] = m;
    }
    __syncthreads();
    const bool masked = (wred[0] + wred[1]) == 0.0f;

    // ---- phase 1: S = Q K^T (3-pass split) ----
    uint32_t aqh[4][4], aql[4][4];
#pragma unroll
    for (int kt = 0; kt < 4; kt++) {
        const int b0 = (w * 16 + g) * PW + 8 * kt + c;
        const int b1 = (w * 16 + g + 8) * PW + 8 * kt + c;
        aqh[kt][0] = QH[b0];     aqh[kt][1] = QH[b1];
        aqh[kt][2] = QH[b0 + 4]; aqh[kt][3] = QH[b1 + 4];
        aql[kt][0] = QL[b0];     aql[kt][1] = QL[b1];
        aql[kt][2] = QL[b0 + 4]; aql[kt][3] = QL[b1 + 4];
    }

    float Sd[8][4];
#pragma unroll
    for (int nf = 0; nf < 8; nf++)
#pragma unroll
        for (int q = 0; q < 4; q++) Sd[nf][q] = 0.0f;

#pragma unroll
    for (int nf = 0; nf < 8; nf++) {
#pragma unroll
        for (int kt = 0; kt < 4; kt++) {
            const int rb = (8 * nf + g) * PW + 8 * kt + c;
            uint32_t bh[2] = {KH[rb], KH[rb + 4]};
            uint32_t bl[2] = {KL[rb], KL[rb + 4]};
            mma_bf16(Sd[nf], aqh[kt], bh);
            mma_bf16(Sd[nf], aqh[kt], bl);
            mma_bf16(Sd[nf], aql[kt], bh);
        }
    }
    __syncthreads();   // all warps done reading Q/K planes

    // ---- scale + mask + register split of S into A-fragments ----
    uint32_t sh[4][4], sl[4][4];
#pragma unroll
    for (int nf = 0; nf < 8; nf++)
#pragma unroll
        for (int q = 0; q < 4; q++)
            Sd[nf][q] = masked ? -1e9f : Sd[nf][q] * 0.125f;
#pragma unroll
    for (int kt2 = 0; kt2 < 4; kt2++) {
        split2(Sd[2 * kt2][0],     Sd[2 * kt2][1],     sh[kt2][0], sl[kt2][0]);
        split2(Sd[2 * kt2][2],     Sd[2 * kt2][3],     sh[kt2][1], sl[kt2][1]);
        split2(Sd[2 * kt2 + 1][0], Sd[2 * kt2 + 1][1], sh[kt2][2], sl[kt2][2]);
        split2(Sd[2 * kt2 + 1][2], Sd[2 * kt2 + 1][3], sh[kt2][3], sl[kt2][3]);
    }

    // ---- transpose+split V: VS[cc][j] -> VT planes [j][cc] (overlay Q area) ----
    {
        const int j = tid >> 1;
        const int ch = tid & 1;
#pragma unroll 4
        for (int p = 0; p < 16; p++) {
            const int cc = ch * 32 + 2 * p;
            float v0 = VS[cc * 68 + j];
            float v1 = VS[(cc + 1) * 68 + j];
            uint32_t h2, l2;
            split2(v0, v1, h2, l2);
            VTH[j * PW + ch * 16 + p] = h2;
            VTL[j * PW + ch * 16 + p] = l2;
        }
    }
    __syncthreads();

    // ---- phase 2: O = S V (3-pass split, A from registers) ----
    float Od[8][4];
#pragma unroll
    for (int jt = 0; jt < 8; jt++)
#pragma unroll
        for (int q = 0; q < 4; q++) Od[jt][q] = 0.0f;

#pragma unroll
    for (int jt = 0; jt < 8; jt++) {
#pragma unroll
        for (int kt2 = 0; kt2 < 4; kt2++) {
            const int rb = (8 * jt + g) * PW + 8 * kt2 + c;
            uint32_t bh[2] = {VTH[rb], VTH[rb + 4]};
            uint32_t bl[2] = {VTL[rb], VTL[rb + 4]};
            mma_bf16(Od[jt], sh[kt2], bh);
            mma_bf16(Od[jt], sh[kt2], bl);
            mma_bf16(Od[jt], sl[kt2], bh);
        }
    }

    // ---- softmax over j (row b spread across the 4 c-lanes) ----
    float mx0 = -3.4e38f, mx1 = -3.4e38f;
#pragma unroll
    for (int jt = 0; jt < 8; jt++) {
        mx0 = fmaxf(mx0, fmaxf(Od[jt][0], Od[jt][1]));
        mx1 = fmaxf(mx1, fmaxf(Od[jt][2], Od[jt][3]));
    }
    mx0 = fmaxf(mx0, __shfl_xor_sync(0xffffffffu, mx0, 1));
    mx0 = fmaxf(mx0, __shfl_xor_sync(0xffffffffu, mx0, 2));
    mx1 = fmaxf(mx1, __shfl_xor_sync(0xffffffffu, mx1, 1));
    mx1 = fmaxf(mx1, __shfl_xor_sync(0xffffffffu, mx1, 2));
    float s0 = 0.0f, s1 = 0.0f;
#pragma unroll
    for (int jt = 0; jt < 8; jt++) {
        Od[jt][0] = __expf(Od[jt][0] - mx0); s0 += Od[jt][0];
        Od[jt][1] = __expf(Od[jt][1] - mx0); s0 += Od[jt][1];
        Od[jt][2] = __expf(Od[jt][2] - mx1); s1 += Od[jt][2];
        Od[jt][3] = __expf(Od[jt][3] - mx1); s1 += Od[jt][3];
    }
    s0 += __shfl_xor_sync(0xffffffffu, s0, 1);
    s0 += __shfl_xor_sync(0xffffffffu, s0, 2);
    s1 += __shfl_xor_sync(0xffffffffu, s1, 1);
    s1 += __shfl_xor_sync(0xffffffffu, s1, 2);
    const float inv0 = 1.0f / s0;
    const float inv1 = 1.0f / s1;

    // ---- stage split output (overlay K area), then coalesced writeout ----
    {
        const int r0 = w * 16 + g;
        const int r1 = r0 + 8;
#pragma unroll
        for (int jt = 0; jt < 8; jt++) {
            uint32_t h2, l2;
            split2(Od[jt][0] * inv0, Od[jt][1] * inv0, h2, l2);
            SH[r0 * PW + 4 * jt + c] = h2;
            SL[r0 * PW + 4 * jt + c] = l2;
            split2(Od[jt][2] * inv1, Od[jt][3] * inv1, h2, l2);
            SH[r1 * PW + 4 * jt + c] = h2;
            SL[r1 * PW + 4 * jt + c] = l2;
        }
    }
    __syncthreads();

    uint4* dst = Ci + head_base / 4;
#pragma unroll
    for (int it = 0; it < 8; it++) {
        const int idx = tid + 128 * it;          // 0..1023
        const int row = idx >> 4;
        const int q4 = idx & 15;
        uint32_t h0 = SH[row * PW + 2 * q4], h1 = SH[row * PW + 2 * q4 + 1];
        uint32_t l0 = SL[row * PW + 2 * q4], l1 = SL[row * PW + 2 * q4 + 1];
        dst[(size_t)row * (DM / 4) + q4] = make_uint4(h0, h1, l0, l1);
    }
}

extern "C" void kernel_launch(void* const* d_in, const int* in_sizes, int n_in,
                              void* d_out, int out_size) {
    const float* kin  = (const float*)d_in[0];
    const float* vin  = (const float*)d_in[1];
    const int*   mask = (const int*)  d_in[2];
    const float* gt   = (const float*)d_in[3];
    const float* Wq   = (const float*)d_in[4];
    const float* bq   = (const float*)d_in[5];
    const float* Wk   = (const float*)d_in[6];
    const float* bk   = (const float*)d_in[7];
    const float* Wv   = (const float*)d_in[8];
    const float* bv   = (const float*)d_in[9];
    const float* Wo   = (const float*)d_in[10];
    const float* bo   = (const float*)d_in[11];
    float* out = (float*)d_out;

    float *pq, *pk, *pv;
    cudaGetSymbolAddress((void**)&pq, g_q);
    cudaGetSymbolAddress((void**)&pk, g_k);
    cudaGetSymbolAddress((void**)&pv, g_v);
    uint4 *ci, *wqi, *wki, *wvi, *woi;
    cudaGetSymbolAddress((void**)&ci,  g_ci);
    cudaGetSymbolAddress((void**)&wqi, g_wqi);
    cudaGetSymbolAddress((void**)&wki, g_wki);
    cudaGetSymbolAddress((void**)&wvi, g_wvi);
    cudaGetSymbolAddress((void**)&woi, g_woi);

    cudaFuncSetAttribute(gemm_mixed,    cudaFuncAttributeMaxDynamicSharedMemorySize, SMEM_TOTAL);
    cudaFuncSetAttribute(gemm_presplit, cudaFuncAttributeMaxDynamicSharedMemorySize, SMEM_TOTAL);
    cudaFuncSetAttribute(attn_kernel,   cudaFuncAttributeMaxDynamicSharedMemorySize, ATTN_SMEM_BYTES);

    const int nW4 = DM * DM / 4;   // 262144
    split_kernel<<<nW4 / 256, 256>>>(Wq, wqi, nW4);
    split_kernel<<<nW4 / 256, 256>>>(Wk, wki, nW4);
    split_kernel<<<nW4 / 256, 256>>>(Wv, wvi, nW4);
    split_kernel<<<nW4 / 256, 256>>>(Wo, woi, nW4);

    dim3 gg(DM / BN, MTOT / BM);   // (8, 512)
    gemm_mixed<<<gg, GEMM_THREADS, SMEM_TOTAL>>>(gt,  wqi, bq, pq);
    gemm_mixed<<<gg, GEMM_THREADS, SMEM_TOTAL>>>(kin, wki, bk, pk);
    gemm_mixed<<<gg, GEMM_THREADS, SMEM_TOTAL>>>(vin, wvi, bv, pv);
    attn_kernel<<<dim3(SLEN, NH), 128, ATTN_SMEM_BYTES>>>(mask, pq, pk, pv, ci);
    gemm_presplit<<<gg, GEMM_THREADS, SMEM_TOTAL>>>(ci, woi, bo, out);
}